// round 6
// baseline (speedup 1.0000x reference)
#include <cuda_runtime.h>
#include <cuda_bf16.h>

// CBC_34033320854004 — R6: packed fma.rn.f32x2 (halve fma-pipe issues) + __ldcs streaming
// x           : [B, 1024] f32
// components  : [5, 1024] f32
// reasonings  : [5, 3, 2] f32
// out (probs) : [B, 3]    f32

#define D_DIM 1024
#define K_DIM 5
#define C_DIM 3
#define THREADS 256
#define ROWS_PER_TASK 4
#define F4_PER_ROW (D_DIM / 4)         // 256 16-byte chunks per row
#define F4_PER_LANE (F4_PER_ROW / 32)  // 8 chunks per lane
#define NUM_SMS 148
#define CTAS_PER_SM 3
#define GRID_PERSIST (NUM_SMS * CTAS_PER_SM)   // 444

typedef unsigned long long u64;

// packed f32x2 fma: d.lo += a.lo*b.lo ; d.hi += a.hi*b.hi   (FFMA2, PTX-only)
__device__ __forceinline__ void fma2(u64& d, u64 a, u64 b) {
    asm("fma.rn.f32x2 %0, %1, %2, %0;" : "+l"(d) : "l"(a), "l"(b));
}
__device__ __forceinline__ float f2sum(u64 v) {
    float lo, hi;
    asm("mov.b64 {%0, %1}, %2;" : "=f"(lo), "=f"(hi) : "l"(v));
    return lo + hi;
}

__device__ unsigned int g_ticket;
__global__ void reset_ticket_kernel() { g_ticket = 0u; }

__global__ __launch_bounds__(THREADS, CTAS_PER_SM)
void cbc_kernel(const float* __restrict__ x,
                const float* __restrict__ comps,
                const float* __restrict__ reas,
                float* __restrict__ out,
                int B)
{
    __shared__ float s_comp[K_DIM * D_DIM];   // 20 KB
    __shared__ float s_c2[K_DIM];
    __shared__ float s_W[C_DIM][K_DIM];       // pk - nk
    __shared__ float s_bias[C_DIM];           // sum_k nk
    __shared__ float s_rden[C_DIM];           // 1 / sum_k (pk + nk)

    const int tid  = threadIdx.x;
    const int wid  = tid >> 5;
    const int lane = tid & 31;

    // ---- stage components into shared (once per persistent CTA) ----
    {
        const float4* src = reinterpret_cast<const float4*>(comps);
        float4* dst = reinterpret_cast<float4*>(s_comp);
        #pragma unroll
        for (int i = tid; i < K_DIM * F4_PER_ROW; i += THREADS)
            dst[i] = src[i];
    }

    // ---- reasonings -> W, bias, rden (tiny; one thread) ----
    if (tid == 0) {
        #pragma unroll
        for (int c = 0; c < C_DIM; ++c) {
            float bias = 0.f, den = 0.f;
            #pragma unroll
            for (int k = 0; k < K_DIM; ++k) {
                float A  = reas[(k * C_DIM + c) * 2 + 0];
                float Bn = reas[(k * C_DIM + c) * 2 + 1];
                A  = fminf(fmaxf(A,  0.f), 1.f);
                Bn = fminf(fmaxf(Bn, 0.f), 1.f);
                float pk = A;
                float nk = (1.f - A) * Bn;
                s_W[c][k] = pk - nk;
                bias += nk;
                den  += pk + nk;
            }
            s_bias[c] = bias;
            s_rden[c] = 1.f / den;
        }
    }
    __syncthreads();

    // ---- c2[k]: one warp per component ----
    if (wid < K_DIM) {
        float acc = 0.f;
        const float4* cp = reinterpret_cast<const float4*>(s_comp + wid * D_DIM);
        #pragma unroll
        for (int j = 0; j < F4_PER_LANE; ++j) {
            float4 v = cp[lane + 32 * j];
            acc += v.x * v.x + v.y * v.y + v.z * v.z + v.w * v.w;
        }
        #pragma unroll
        for (int off = 16; off; off >>= 1)
            acc += __shfl_xor_sync(0xffffffffu, acc, off);
        if (lane == 0) s_c2[wid] = acc;
    }
    __syncthreads();

    const ulonglong2* __restrict__ sbase =
        reinterpret_cast<const ulonglong2*>(s_comp) + lane;
    const int n_tasks = B / ROWS_PER_TASK;

    // ---- persistent per-warp work loop over 4-row tasks ----
    for (;;) {
        unsigned int t;
        if (lane == 0) t = atomicAdd(&g_ticket, 1u);
        t = __shfl_sync(0xffffffffu, t, 0);
        if (t >= (unsigned int)n_tasks) break;
        const int r0 = (int)t * ROWS_PER_TASK;

        const ulonglong2* __restrict__ xbase =
            reinterpret_cast<const ulonglong2*>(x + (size_t)r0 * D_DIM) + lane;

        // acc2 layout: [row][0] = xx (packed), [row][1+k] = dot_k (packed)
        u64 acc2[ROWS_PER_TASK][K_DIM + 1];
        #pragma unroll
        for (int rr = 0; rr < ROWS_PER_TASK; ++rr)
            #pragma unroll
            for (int i = 0; i <= K_DIM; ++i) acc2[rr][i] = 0ull;

        #pragma unroll
        for (int j = 0; j < F4_PER_LANE; ++j) {
            ulonglong2 v[ROWS_PER_TASK];
            #pragma unroll
            for (int rr = 0; rr < ROWS_PER_TASK; ++rr)
                v[rr] = __ldcs(xbase + rr * F4_PER_ROW + 32 * j);  // imm offsets, streaming
            #pragma unroll
            for (int rr = 0; rr < ROWS_PER_TASK; ++rr) {
                fma2(acc2[rr][0], v[rr].x, v[rr].x);
                fma2(acc2[rr][0], v[rr].y, v[rr].y);
            }
            #pragma unroll
            for (int k = 0; k < K_DIM; ++k) {
                ulonglong2 cv = sbase[k * F4_PER_ROW + 32 * j];    // imm offsets
                #pragma unroll
                for (int rr = 0; rr < ROWS_PER_TASK; ++rr) {
                    fma2(acc2[rr][1 + k], v[rr].x, cv.x);
                    fma2(acc2[rr][1 + k], v[rr].y, cv.y);
                }
            }
        }

        // collapse packed accumulators, then butterfly-reduce 24 floats
        float acc[ROWS_PER_TASK][K_DIM + 1];
        #pragma unroll
        for (int rr = 0; rr < ROWS_PER_TASK; ++rr)
            #pragma unroll
            for (int i = 0; i <= K_DIM; ++i)
                acc[rr][i] = f2sum(acc2[rr][i]);

        #pragma unroll
        for (int rr = 0; rr < ROWS_PER_TASK; ++rr)
            #pragma unroll
            for (int i = 0; i <= K_DIM; ++i)
                #pragma unroll
                for (int off = 16; off; off >>= 1)
                    acc[rr][i] += __shfl_xor_sync(0xffffffffu, acc[rr][i], off);

        if (lane == 0) {
            #pragma unroll
            for (int rr = 0; rr < ROWS_PER_TASK; ++rr) {
                const int r = r0 + rr;
                const float xx = acc[rr][0];
                float num[C_DIM];
                #pragma unroll
                for (int c = 0; c < C_DIM; ++c) num[c] = s_bias[c];
                #pragma unroll
                for (int k = 0; k < K_DIM; ++k) {
                    float d2 = xx + s_c2[k] - 2.f * acc[rr][1 + k];
                    d2 = fmaxf(d2, 0.f);
                    float s = __expf(-0.5f * d2);
                    #pragma unroll
                    for (int c = 0; c < C_DIM; ++c) num[c] += s * s_W[c][k];
                }
                #pragma unroll
                for (int c = 0; c < C_DIM; ++c)
                    out[(size_t)r * C_DIM + c] = num[c] * s_rden[c];
            }
        }
    }
}

extern "C" void kernel_launch(void* const* d_in, const int* in_sizes, int n_in,
                              void* d_out, int out_size)
{
    const float* x     = (const float*)d_in[0];
    const float* comps = (const float*)d_in[1];
    const float* reas  = (const float*)d_in[2];
    float* out = (float*)d_out;

    const int B = in_sizes[0] / D_DIM;          // 32768

    reset_ticket_kernel<<<1, 1>>>();
    cbc_kernel<<<GRID_PERSIST, THREADS>>>(x, comps, reas, out, B);
}